// round 13
// baseline (speedup 1.0000x reference)
#include <cuda_runtime.h>
#include <cuda.h>
#include <math.h>
#include <stdint.h>

// Fixed shape: H=1024, B=64, T=1024
#define BB 64
#define TS 1024
#define HS 1024
#define TCH 8                        // t per tile
#define NTILES 8192                  // 64 b * 128 t-chunks
#define GRIDN 152
#define NTHR 1024                    // 2 groups x 16 warps
#define DEPTH 3
#define TILE_FLOATS (HS * TCH)       // 8192
#define TILE_BYTES (TILE_FLOATS * 4) // 32 KB
#define L2E 1.44269504088896340736f

// dynamic smem layout (floats):
// [0, 49152)            : 2 groups x DEPTH x TILE_FLOATS ring
// [49152, 51200)        : dhs per group (1024 each)
// [51200, 52224)        : sred per group (512 each: A/B/C/D x [16w][8t])
// [52224, 52288)        : fin per group (32 each: sc8|X8|N8|inv8)
#define F_DH   49152
#define F_SRED 51200
#define F_FIN  52224
#define F_END  52288
#define B_MBAR (F_END * 4)               // 6 mbarriers x 8 B
#define SMEM_BYTES (B_MBAR + 48)         // ~204.3 KB

__device__ __forceinline__ uint32_t smem_u32(const void* p) {
    return (uint32_t)__cvta_generic_to_shared(p);
}
__device__ __forceinline__ void mbar_init(uint32_t a, uint32_t cnt) {
    asm volatile("mbarrier.init.shared.b64 [%0], %1;" :: "r"(a), "r"(cnt) : "memory");
}
#define MB_WAIT(addr, parity) do {                                              \
    uint32_t _m = (addr), _p = (parity), _d;                                    \
    asm volatile("{\n\t.reg .pred p;\n\t"                                       \
        "mbarrier.try_wait.parity.acquire.cta.shared::cta.b64 p, [%1], %2;\n\t" \
        "selp.b32 %0, 1, 0, p;\n\t}" : "=r"(_d) : "r"(_m), "r"(_p) : "memory"); \
    if (!_d) {                                                                  \
        asm volatile("{\n\t.reg .pred P1;\n\tW%=:\n\t"                          \
            "mbarrier.try_wait.parity.acquire.cta.shared::cta.b64 P1, [%0], %1, 0x989680;\n\t" \
            "@P1 bra.uni D%=;\n\tbra.uni W%=;\n\tD%=:\n\t}"                     \
            :: "r"(_m), "r"(_p) : "memory");                                    \
    }                                                                           \
} while (0)

// One 32KB tile (tile id m) into smem address dst: expect_tx + 4 x 3D TMA.
__device__ __forceinline__ void tma_issue(const CUtensorMap& tmap, uint32_t dst,
                                          uint32_t mb, int m) {
    const int c = m & 127, b = m >> 7;
    asm volatile("mbarrier.arrive.expect_tx.shared.b64 _, [%0], %1;"
                 :: "r"(mb), "r"((uint32_t)TILE_BYTES) : "memory");
    #pragma unroll
    for (int k = 0; k < 4; ++k) {
        asm volatile(
            "cp.async.bulk.tensor.3d.shared::cta.global.tile.mbarrier::complete_tx::bytes "
            "[%0], [%1, {%2, %3, %4}], [%5];"
            :: "r"(dst + (uint32_t)k * 8192), "l"(&tmap),
               "r"(c * TCH), "r"(b), "r"(k * 256), "r"(mb) : "memory");
    }
}

// In-register 8x8 transpose-reduce over lanes' low-3 bits (hw = lane & 7).
__device__ __forceinline__ void tr_reduce8(float* a, int hw) {
    #pragma unroll
    for (int s = 4; s >= 1; s >>= 1) {
        const bool up = (hw & s) != 0;
        #pragma unroll
        for (int i = 0; i < s; ++i) {
            const float give = up ? a[i] : a[i + s];
            const float keep = up ? a[i + s] : a[i];
            const float got  = __shfl_xor_sync(0xffffffffu, give, s);
            a[i] = keep + got;
        }
    }
}

__global__ void __launch_bounds__(1024)
zero_out(float* __restrict__ out) {
    out[blockIdx.x * 1024 + threadIdx.x] = 0.0f;
}

__global__ void __launch_bounds__(NTHR, 1)
attn_main(const __grid_constant__ CUtensorMap tmap,
          const float* __restrict__ dh, float* __restrict__ out) {
    extern __shared__ float smem[];
    const uint32_t sb = smem_u32(smem);

    const int tid = threadIdx.x;
    const int w = tid >> 5, l = tid & 31;
    const int g = w >> 4, wg = w & 15;     // group 0/1, warp-in-group
    const int barid = g + 1;               // named barrier per group
    const int t = l & 7, hr = l >> 3;
    const int rg = wg * 4 + hr;            // rows rg + 64*i, i < 16

    float* ring  = smem + g * (DEPTH * TILE_FLOATS);
    float* dhs   = smem + F_DH + g * 1024;
    float* sredA = smem + F_SRED + g * 512;   // [16 w][8 t]
    float* sredB = sredA + 128;
    float* sredC = sredB + 128;
    float* sredD = sredC + 128;
    float* fin   = smem + F_FIN + g * 32;     // sc8 | X8 | N8 | inv8
    const uint32_t MBg = sb + B_MBAR + (uint32_t)g * DEPTH * 8;
    const uint32_t RBg = sb + (uint32_t)g * DEPTH * TILE_BYTES;

    // CTA tile range; group g owns local indices j with j%2 == g
    const int start = (int)(((long long)blockIdx.x * NTILES) / GRIDN);
    const int end   = (int)(((long long)(blockIdx.x + 1) * NTILES) / GRIDN);
    const int ntot  = end - start;
    const int ng    = (ntot - g + 1) >> 1;   // owned tiles: n = start + 2k + g

    if (tid == 0) {
        #pragma unroll
        for (int s = 0; s < 2 * DEPTH; ++s)
            mbar_init(sb + B_MBAR + s * 8, 1);
    }
    __syncthreads();   // the ONLY full-CTA sync; groups free-run after this

    if (wg == 0 && l == 0)
        for (int kk = 0; kk < DEPTH && kk < ng; ++kk)
            tma_issue(tmap, RBg + kk * TILE_BYTES, MBg + kk * 8,
                      start + 2 * kk + g);

    float acc[16];
    #pragma unroll
    for (int i = 0; i < 16; ++i) acc[i] = 0.0f;

    int bcur = -1;
    for (int k = 0; k < ng; ++k) {
        const int n = start + 2 * k + g;
        const int b = n >> 7;
        const int s = k % DEPTH;

        if (b != bcur) {                 // <= 2 times per group
            if (bcur >= 0) {
                tr_reduce8(acc, t);
                tr_reduce8(acc + 8, t);
                atomicAdd(out + bcur * HS + rg + 64 * t,       acc[0]);
                atomicAdd(out + bcur * HS + rg + 64 * (8 + t), acc[8]);
                #pragma unroll
                for (int i = 0; i < 16; ++i) acc[i] = 0.0f;
            }
            const int tig = tid - g * 512;
            if (tig < 256)
                reinterpret_cast<float4*>(dhs)[tig] =
                    __ldg(reinterpret_cast<const float4*>(dh + b * HS) + tig);
            bcur = b;
            asm volatile("bar.sync %0, 512;" :: "r"(barid) : "memory");
        }
        MB_WAIT(MBg + s * 8, (k / DEPTH) & 1);

        // ---- stat pass: tile slice -> registers, fused dot/max/min ----
        // element (row, tt) at tile[row*8 + tt]; bank = (rg*8+t)%32 = l.
        const float* tp = ring + s * TILE_FLOATS + rg * TCH + t;
        const float* dp = dhs + rg;
        float v[16];
        float sp = 0.f, mx = -INFINITY, mn = INFINITY;
        #pragma unroll
        for (int i = 0; i < 16; ++i) {
            v[i] = tp[i * 64 * TCH];
            sp = fmaf(v[i], dp[i * 64], sp);
            mx = fmaxf(mx, v[i]);
            mn = fminf(mn, v[i]);
        }
        // fold across the 4 hr groups (lane bits 3,4)
        sp += __shfl_xor_sync(~0u, sp, 8);
        sp += __shfl_xor_sync(~0u, sp, 16);
        mx = fmaxf(mx, __shfl_xor_sync(~0u, mx, 8));
        mx = fmaxf(mx, __shfl_xor_sync(~0u, mx, 16));
        mn = fminf(mn, __shfl_xor_sync(~0u, mn, 8));
        mn = fminf(mn, __shfl_xor_sync(~0u, mn, 16));
        if (l < 8) {
            sredA[wg * 8 + l] = sp;
            sredB[wg * 8 + l] = mx;
            sredC[wg * 8 + l] = mn;
        }
        asm volatile("bar.sync %0, 512;" :: "r"(barid) : "memory");  // #1

        // refill slot s (stat pass done -> slot free)
        if (wg == 0 && l == 0 && k + DEPTH < ng)
            tma_issue(tmap, RBg + s * TILE_BYTES, MBg + s * 8,
                      start + 2 * (k + DEPTH) + g);

        // warps 0/1/2 of the group fold sum/max/min in parallel
        if (wg < 3 && l < 8) {
            if (wg == 0) {
                float sc = 0.f;
                #pragma unroll
                for (int w2 = 0; w2 < 16; ++w2) sc += sredA[w2 * 8 + l];
                fin[l] = sc;
            } else if (wg == 1) {
                float X = -INFINITY;
                #pragma unroll
                for (int w2 = 0; w2 < 16; ++w2) X = fmaxf(X, sredB[w2 * 8 + l]);
                fin[8 + l] = X;
            } else {
                float N = INFINITY;
                #pragma unroll
                for (int w2 = 0; w2 < 16; ++w2) N = fminf(N, sredC[w2 * 8 + l]);
                fin[16 + l] = N;
            }
        }
        asm volatile("bar.sync %0, 512;" :: "r"(barid) : "memory");  // #2

        const float sc = fin[t];
        const float X  = fin[8 + t];
        const float N  = fin[16 + t];
        const float M  = (sc >= 0.f) ? X * sc : N * sc;   // exact max_h(v*s)
        const float scF = sc * L2E;
        const float MF  = M * L2E;

        // ---- exp2 on registers + denominator (2 chains) ----
        float d0 = 0.f, d1 = 0.f;
        #pragma unroll
        for (int i = 0; i < 16; i += 2) {
            v[i]     = exp2f(fmaf(v[i],     scF, -MF));
            v[i + 1] = exp2f(fmaf(v[i + 1], scF, -MF));
            d0 += v[i];
            d1 += v[i + 1];
        }
        float ds = d0 + d1;
        ds += __shfl_xor_sync(~0u, ds, 8);
        ds += __shfl_xor_sync(~0u, ds, 16);
        if (l < 8) sredD[wg * 8 + l] = ds;
        asm volatile("bar.sync %0, 512;" :: "r"(barid) : "memory");  // #3

        if (wg == 0 && l < 8) {
            float d = 0.f;
            #pragma unroll
            for (int w2 = 0; w2 < 16; ++w2) d += sredD[w2 * 8 + l];
            fin[24 + l] = 1.0f / d;
        }
        asm volatile("bar.sync %0, 512;" :: "r"(barid) : "memory");  // #4

        const float inv = fin[24 + t];
        #pragma unroll
        for (int i = 0; i < 16; ++i)
            acc[i] = fmaf(v[i], inv, acc[i]);
    }

    // final flush
    if (bcur >= 0) {
        tr_reduce8(acc, t);
        tr_reduce8(acc + 8, t);
        atomicAdd(out + bcur * HS + rg + 64 * t,       acc[0]);
        atomicAdd(out + bcur * HS + rg + 64 * (8 + t), acc[8]);
    }
}

extern "C" void kernel_launch(void* const* d_in, const int* in_sizes, int n_in,
                              void* d_out, int out_size) {
    const float* dh  = (const float*)d_in[0];
    const float* enc = (const float*)d_in[1];
    if (n_in >= 2 && in_sizes[0] > in_sizes[1]) {
        enc = (const float*)d_in[0];
        dh  = (const float*)d_in[1];
    }
    float* out = (float*)d_out;

    typedef CUresult (*EncodeFn)(
        CUtensorMap*, CUtensorMapDataType, cuuint32_t, void*,
        const cuuint64_t*, const cuuint64_t*, const cuuint32_t*, const cuuint32_t*,
        CUtensorMapInterleave, CUtensorMapSwizzle, CUtensorMapL2promotion,
        CUtensorMapFloatOOBfill);
    void* fp = nullptr;
    cudaDriverEntryPointQueryResult qres;
#if CUDART_VERSION >= 12050
    cudaGetDriverEntryPointByVersion("cuTensorMapEncodeTiled", &fp, 12030,
                                     cudaEnableDefault, &qres);
#else
    cudaGetDriverEntryPoint("cuTensorMapEncodeTiled", &fp, cudaEnableDefault, &qres);
#endif
    CUtensorMap tmap;
    {
        EncodeFn fn = (EncodeFn)fp;
        cuuint64_t dims[3]    = {TS, BB, HS};
        cuuint64_t strides[2] = {TS * 4ull, (cuuint64_t)BB * TS * 4ull};
        cuuint32_t box[3]     = {TCH, 1, 256};
        cuuint32_t es[3]      = {1, 1, 1};
        fn(&tmap, CU_TENSOR_MAP_DATA_TYPE_FLOAT32, 3, (void*)enc,
           dims, strides, box, es,
           CU_TENSOR_MAP_INTERLEAVE_NONE, CU_TENSOR_MAP_SWIZZLE_NONE,
           CU_TENSOR_MAP_L2_PROMOTION_L2_128B, CU_TENSOR_MAP_FLOAT_OOB_FILL_NONE);
    }

    cudaFuncSetAttribute(attn_main,
                         cudaFuncAttributeMaxDynamicSharedMemorySize, SMEM_BYTES);
    zero_out<<<64, 1024>>>(out);
    attn_main<<<GRIDN, NTHR, SMEM_BYTES>>>(tmap, dh, out);
}